// round 12
// baseline (speedup 1.0000x reference)
#include <cuda_runtime.h>

#define NN 32
#define CC 256
#define SS 30
#define HWD 256        // 16*16 pixels per frame
#define PP 16          // parts
#define CT 16          // channels per tile
#define PIT 260        // pitch: 16B-aligned rows, 2-way worst-case LDS
#define TILES 4        // tiles per block (block covers 64 channels)
#define SLICES 4       // channel slices per frame

#define CP_ASYNC16(dst, src) \
    asm volatile("cp.async.cg.shared.global [%0], [%1], 16;" :: "r"(dst), "l"(src) : "memory")
#define CP_COMMIT() asm volatile("cp.async.commit_group;" ::: "memory")
#define CP_WAIT(n)  asm volatile("cp.async.wait_group %0;" :: "n"(n) : "memory")

__global__ __launch_bounds__(256, 6)
void part_pool_kernel(const float* __restrict__ x,
                      const void* __restrict__ labels_raw,
                      float* __restrict__ out)
{
    extern __shared__ float tiles[];      // 2 * CT*PIT floats = 33,280 B
    __shared__ float pooled[2 * CT * 17];
    __shared__ unsigned int pk4w[(HWD + PP * 4) / 4];  // byte pixel lists, 4-aligned starts
    __shared__ int off4[PP], fill[PP];

    unsigned char* pk4 = (unsigned char*)pk4w;

    const int bid = blockIdx.x;           // 0..3839
    const int f   = bid >> 2;             // frame
    const int q   = bid & 3;              // channel slice (64 channels)
    const int n = f / SS;
    const int s = f % SS;
    const int t = threadIdx.x;
    const int w = t >> 5;
    const int l = t & 31;

    // base of this block's channel range for frame (n,s)
    const float* xf = x + ((size_t)(n * CC + q * (TILES * CT)) * SS + s) * HWD;
    const unsigned stile = (unsigned)__cvta_generic_to_shared(tiles);

    // 16B cp.async: thread t loads channel t>>4, 4 groups of 4 pixels (coalesced)
    const int lcl = t >> 4;
    const int lg  = t & 15;
    #define LOAD_TILE(tt, buf) do {                                            \
        const float* _row = xf + (size_t)((tt) * CT + lcl) * (SS * HWD);       \
        unsigned _dst = stile + (unsigned)(((buf) * CT + lcl) * (PIT * 4));    \
        _Pragma("unroll")                                                      \
        for (int _k = 0; _k < 4; _k++) {                                       \
            int _g = lg + 16 * _k;                                             \
            CP_ASYNC16(_dst + _g * 16, _row + _g * 4);                         \
        }                                                                      \
        CP_COMMIT();                                                           \
    } while (0)

    // ---- issue the first tile-pair BEFORE the prologue (no label dependence):
    // overlaps all bucketing latency with the first 32 KB of DRAM traffic.
    LOAD_TILE(0, 0);
    LOAD_TILE(1, 1);

    // ---- fused label-dtype detection (frame-0 region, in-bounds both layouts):
    // int64 little-endian labels 0..15 -> odd 32-bit words all zero.
    if (t < PP) fill[t] = 0;
    const int oddw = ((const int*)labels_raw)[2 * t + 1];
    const int lab64 = !__syncthreads_or(oddw != 0);   // also orders fill init

    // ---- per-frame label bucketing (single atomic phase) ----
    int myl;
    if (lab64) myl = (int)((const long long*)labels_raw)[(size_t)f * HWD + t];
    else       myl = ((const int*)labels_raw)[(size_t)f * HWD + t];
    myl &= (PP - 1);
    const int pos = atomicAdd(&fill[myl], 1);
    __syncthreads();                      // fill[p] == cnt[p] final

    // per-lane fixed roles: half-warp owns one part, lane&15 = channel in tile
    const int p  = (w << 1) | (l >> 4);   // part 0..15
    const int cl = l & 15;                // channel-in-tile
    const int cN = fill[p];
    const float rc = (cN > 0) ? (1.0f / (float)cN) : 0.0f;

    if (t == 0) {
        int acc = 0;
        #pragma unroll
        for (int pp = 0; pp < PP; pp++) { off4[pp] = acc; acc += (fill[pp] + 3) & ~3; }
    }
    __syncthreads();                      // off4[] ready
    pk4[off4[myl] + pos] = (unsigned char)t;   // byte pixel list write
    // pk4 visibility to other warps: covered by the first pair-ready sync.

    const unsigned int* mylist = pk4w + (off4[p] >> 2);
    const int kW = cN >> 2;               // full 4-pixel words
    const int kR = cN & 3;                // tail pixels in final word

    #pragma unroll
    for (int pr = 0; pr < TILES / 2; pr++) {
        CP_WAIT(0);                       // both tiles of this pair landed
        __syncthreads();                  // visible to all

        // buffer 0 = even tile, buffer 1 = odd tile; shared gather address,
        // second read via constant +CT*PIT immediate offset (no extra ALU).
        const float* tb = tiles + cl * PIT;

        float sum0 = 0.0f, mx0 = -3.0e38f;
        float sum1 = 0.0f, mx1 = -3.0e38f;
        #pragma unroll 2
        for (int k = 0; k < kW; k++) {
            unsigned u = mylist[k];       // 1 broadcast LDS -> 4 pixel ids
            int pa = u & 255u, pb = (u >> 8) & 255u,
                pc = (u >> 16) & 255u, pd = u >> 24;
            float a0 = tb[pa],            b0 = tb[pb];
            float c0 = tb[pc],            d0 = tb[pd];
            float a1 = tb[pa + CT * PIT], b1 = tb[pb + CT * PIT];
            float c1 = tb[pc + CT * PIT], d1 = tb[pd + CT * PIT];
            sum0 += (a0 + b0) + (c0 + d0);
            sum1 += (a1 + b1) + (c1 + d1);
            mx0 = fmaxf(fmaxf(fmaxf(a0, b0), fmaxf(c0, d0)), mx0);
            mx1 = fmaxf(fmaxf(fmaxf(a1, b1), fmaxf(c1, d1)), mx1);
        }
        if (kR) {                         // tail: only written bytes extracted
            unsigned u = mylist[kW];
            #pragma unroll
            for (int j = 0; j < 3; j++) {
                if (j < kR) {
                    int px = (u >> (8 * j)) & 255u;
                    float v0 = tb[px], v1 = tb[px + CT * PIT];
                    sum0 += v0; mx0 = fmaxf(mx0, v0);
                    sum1 += v1; mx1 = fmaxf(mx1, v1);
                }
            }
        }

        float r0 = 0.0f, r1 = 0.0f;
        if (cN > 0) {
            r0 = sum0 * rc + fmaxf(mx0, -100.0f);   // mean + amax(incl -100)
            r1 = sum1 * rc + fmaxf(mx1, -100.0f);
        }
        pooled[cl * 17 + p]           = r0;
        pooled[CT * 17 + cl * 17 + p] = r1;

        __syncthreads();                  // pooled ready AND both buffers consumed

        // coalesced stores: thread t -> (channel t>>4, part t&15), both tiles
        {
            int cc = t >> 4;
            int pp = t & 15;
            int c0 = q * (TILES * CT) + pr * (2 * CT) + cc;
            out[((size_t)(n * CC + c0) * SS + s) * PP + pp] =
                pooled[cc * 17 + pp];
            out[((size_t)(n * CC + c0 + CT) * SS + s) * PP + pp] =
                pooled[CT * 17 + cc * 17 + pp];
        }

        // refill both buffers with the next pair (all warps done reading above)
        if (pr + 1 < TILES / 2) {
            LOAD_TILE(2 * pr + 2, 0);
            LOAD_TILE(2 * pr + 3, 1);
        }
    }
    #undef LOAD_TILE
}

extern "C" void kernel_launch(void* const* d_in, const int* in_sizes, int n_in,
                              void* d_out, int out_size)
{
    const float* x      = (const float*)d_in[0];
    const void*  labels = d_in[1];
    float*       out    = (float*)d_out;

    cudaFuncSetAttribute(part_pool_kernel,
                         cudaFuncAttributeMaxDynamicSharedMemorySize,
                         2 * CT * PIT * 4);

    part_pool_kernel<<<NN * SS * SLICES, 256, 2 * CT * PIT * 4>>>(x, labels, out);
}